// round 4
// baseline (speedup 1.0000x reference)
#include <cuda_runtime.h>
#include <cuda_bf16.h>
#include <cstdint>
#include <math.h>

#define B        64
#define DV       1024
#define NQ       32
#define NS       1024
#define D        128
#define NEG_MASK 1000000.0f
#define ALPHA    0.5f
#define LDP      136            // padded smem row stride (bf16 elems) -> 272 B
#define ROWB     272            // bytes per smem row

// dynamic smem arena (bytes)
#define OFF_AS   0
#define OFF_B0   34816
#define OFF_B1   69632
#define OFF_RED  104448
#define SMEM_TOT 105472

#define KSPLIT   8

__device__ float g_part[KSPLIT * B * B];        // k-split single-vector partials
__device__ float g_mscores[B * B];              // multi-vector scores
__device__ __nv_bfloat162 g_dmb[B * NS * D / 2]; // d_multi in bf16 (16 MB)
__device__ __nv_bfloat162 g_qmb[B * NQ * D / 2]; // q_multi in bf16 (512 KB)

// ---------------------------------------------------------------------------
// PTX helpers
// ---------------------------------------------------------------------------
__device__ __forceinline__ void ldsm_x4(unsigned int* r, unsigned int addr) {
    asm volatile("ldmatrix.sync.aligned.m8n8.x4.shared.b16 {%0,%1,%2,%3}, [%4];"
                 : "=r"(r[0]), "=r"(r[1]), "=r"(r[2]), "=r"(r[3]) : "r"(addr));
}
__device__ __forceinline__ void mma_16816(float* c, const unsigned int* a,
                                          const unsigned int* b) {
    asm volatile("mma.sync.aligned.m16n8k16.row.col.f32.bf16.bf16.f32 "
                 "{%0,%1,%2,%3}, {%4,%5,%6,%7}, {%8,%9}, {%0,%1,%2,%3};"
                 : "+f"(c[0]), "+f"(c[1]), "+f"(c[2]), "+f"(c[3])
                 : "r"(a[0]), "r"(a[1]), "r"(a[2]), "r"(a[3]), "r"(b[0]), "r"(b[1]));
}
__device__ __forceinline__ void cp_async16(unsigned int saddr, const void* gptr) {
    size_t g = __cvta_generic_to_global(gptr);
    asm volatile("cp.async.cg.shared.global [%0], [%1], 16;" :: "r"(saddr), "l"(g));
}
__device__ __forceinline__ void cp_commit() {
    asm volatile("cp.async.commit_group;");
}
template <int N> __device__ __forceinline__ void cp_wait() {
    asm volatile("cp.async.wait_group %0;" :: "n"(N));
}

// ---------------------------------------------------------------------------
// Kernel 0: fp32 -> bf16 conversion of q_multi and d_multi (one pass)
// ---------------------------------------------------------------------------
#define NDM4 (B * NS * D / 4)   // 2097152 float4s of d_multi
#define NQM4 (B * NQ * D / 4)   // 65536 float4s of q_multi
__global__ void __launch_bounds__(256) k_conv(const float4* __restrict__ dm,
                                              const float4* __restrict__ qm) {
    int i = blockIdx.x * 256 + threadIdx.x;
    if (i < NDM4) {
        float4 v = dm[i];
        g_dmb[i * 2]     = __floats2bfloat162_rn(v.x, v.y);
        g_dmb[i * 2 + 1] = __floats2bfloat162_rn(v.z, v.w);
    } else {
        int j = i - NDM4;
        if (j < NQM4) {
            float4 v = qm[j];
            g_qmb[j * 2]     = __floats2bfloat162_rn(v.x, v.y);
            g_qmb[j * 2 + 1] = __floats2bfloat162_rn(v.z, v.w);
        }
    }
}

// ---------------------------------------------------------------------------
// Kernel 1: single-vector partial scores, k-split by 8 (chunks of 128).
// ---------------------------------------------------------------------------
__global__ void __launch_bounds__(256) k_single(const float* __restrict__ q,
                                                const float* __restrict__ d) {
    __shared__ float qs[128];
    const int b   = blockIdx.x;
    const int kc  = blockIdx.y;
    const int tid = threadIdx.x;
    if (tid < 128) qs[tid] = q[b * DV + kc * 128 + tid];
    __syncthreads();

    const int w    = tid >> 5;
    const int lane = tid & 31;
    #pragma unroll
    for (int cc = 0; cc < 8; cc++) {
        const int c = cc * 8 + w;
        const float* dv = d + c * DV + kc * 128;
        float p = 0.0f;
        #pragma unroll
        for (int i = 0; i < 4; i++) {
            p += qs[lane + i * 32] * dv[lane + i * 32];
        }
        #pragma unroll
        for (int o = 16; o; o >>= 1) {
            p += __shfl_xor_sync(0xffffffffu, p, o);
        }
        if (lane == 0) g_part[(kc * B + b) * B + c] = p;
    }
}

// ---------------------------------------------------------------------------
// Kernel 2: multi-vector late interaction, bf16 mma.sync, cp.async pipeline.
// grid (16 rt, 64 c); 8 warps as 4(m32) x 2(n64) per 128-wide s-tile.
// ---------------------------------------------------------------------------
__global__ void __launch_bounds__(256, 2) k_multi_tc() {
    extern __shared__ char smem_raw[];
    const unsigned int sbase = (unsigned int)__cvta_generic_to_shared(smem_raw);
    const unsigned int sA  = sbase + OFF_AS;
    const unsigned int sB0 = sbase + OFF_B0;
    const unsigned int sB1 = sbase + OFF_B1;
    float* redbuf = (float*)(smem_raw + OFF_RED);   // [2][128]

    const int rt   = blockIdx.x;   // 0..15
    const int c    = blockIdx.y;   // 0..63
    const int tid  = threadIdx.x;
    const int lane = tid & 31;
    const int warp = tid >> 5;
    const int wm   = warp >> 1;    // 0..3
    const int wn   = warp & 1;     // 0..1

    const __nv_bfloat16* Aq = (const __nv_bfloat16*)g_qmb + (size_t)rt * 128 * D;
    const __nv_bfloat16* Dq = (const __nv_bfloat16*)g_dmb + (size_t)c * NS * D;

    // per-thread chunk coords (16 B chunks; 2048 chunks per 128x128 bf16 tile)
    const int ch  = tid & 15;          // chunk along k
    const int rb  = tid >> 4;          // base row (stride 16 over i)

    // issue A tile + B tile 0 as group 0
    #pragma unroll
    for (int i = 0; i < 8; i++) {
        int r = rb + i * 16;
        cp_async16(sA + r * ROWB + ch * 16, Aq + r * D + ch * 8);
    }
    #pragma unroll
    for (int i = 0; i < 8; i++) {
        int s = rb + i * 16;
        cp_async16(sB0 + s * ROWB + ch * 16, Dq + s * D + ch * 8);
    }
    cp_commit();

    // ldmatrix lane addresses
    const int arow = lane & 15;
    const int acol = (lane >> 4) * 8;
    const unsigned int a_addr0 = sA + (wm * 32 + arow) * ROWB + acol * 2;
    const unsigned int a_addr1 = a_addr0 + 16 * ROWB;

    const int g = lane >> 3;           // 0..3
    const unsigned int b_lane_off =
        (unsigned int)((wn * 64 + (g >> 1) * 8 + (lane & 7)) * ROWB + (g & 1) * 16);

    float rmax00 = -3.0e38f, rmax01 = -3.0e38f;
    float rmax10 = -3.0e38f, rmax11 = -3.0e38f;

    for (int st = 0; st < 8; st++) {
        // prefetch next B tile into the other buffer
        if (st < 7) {
            const unsigned int dstB = ((st + 1) & 1) ? sB1 : sB0;
            const __nv_bfloat16* src = Dq + (size_t)(st + 1) * 128 * D;
            #pragma unroll
            for (int i = 0; i < 8; i++) {
                int s = rb + i * 16;
                cp_async16(dstB + s * ROWB + ch * 16, src + s * D + ch * 8);
            }
            cp_commit();
            cp_wait<1>();
        } else {
            cp_wait<0>();
        }
        __syncthreads();

        const unsigned int bufB = (st & 1) ? sB1 : sB0;
        const unsigned int b_base = bufB + b_lane_off;

        float acc[2][8][4];
        #pragma unroll
        for (int mt = 0; mt < 2; mt++) {
            #pragma unroll
            for (int nt = 0; nt < 8; nt++) {
                acc[mt][nt][0] = 0.0f; acc[mt][nt][1] = 0.0f;
                acc[mt][nt][2] = 0.0f; acc[mt][nt][3] = 0.0f;
            }
        }

        #pragma unroll
        for (int kt = 0; kt < 8; kt++) {
            unsigned int a0[4], a1[4];
            ldsm_x4(a0, a_addr0 + kt * 32);
            ldsm_x4(a1, a_addr1 + kt * 32);
            #pragma unroll
            for (int p = 0; p < 4; p++) {
                unsigned int bfr[4];           // {b0,b1} for nt=2p, {b0,b1} for nt=2p+1
                ldsm_x4(bfr, b_base + p * (16 * ROWB) + kt * 32);
                mma_16816(acc[0][2 * p],     a0, bfr);
                mma_16816(acc[1][2 * p],     a1, bfr);
                mma_16816(acc[0][2 * p + 1], a0, bfr + 2);
                mma_16816(acc[1][2 * p + 1], a1, bfr + 2);
            }
        }

        // fold s-tile into running per-row maxima
        float m0 = -3.0e38f, m1 = -3.0e38f, m2 = -3.0e38f, m3 = -3.0e38f;
        #pragma unroll
        for (int nt = 0; nt < 8; nt++) {
            m0 = fmaxf(m0, fmaxf(acc[0][nt][0], acc[0][nt][1]));
            m1 = fmaxf(m1, fmaxf(acc[0][nt][2], acc[0][nt][3]));
            m2 = fmaxf(m2, fmaxf(acc[1][nt][0], acc[1][nt][1]));
            m3 = fmaxf(m3, fmaxf(acc[1][nt][2], acc[1][nt][3]));
        }
        rmax00 = fmaxf(rmax00, m0); rmax01 = fmaxf(rmax01, m1);
        rmax10 = fmaxf(rmax10, m2); rmax11 = fmaxf(rmax11, m3);

        __syncthreads();   // compute done before this buffer is refilled (st+2)
    }

    // cross-lane max: lanes l^1, l^2 hold other columns of the same row
    {
        float v;
        v = rmax00; v = fmaxf(v, __shfl_xor_sync(0xffffffffu, v, 1));
        v = fmaxf(v, __shfl_xor_sync(0xffffffffu, v, 2)); rmax00 = v;
        v = rmax01; v = fmaxf(v, __shfl_xor_sync(0xffffffffu, v, 1));
        v = fmaxf(v, __shfl_xor_sync(0xffffffffu, v, 2)); rmax01 = v;
        v = rmax10; v = fmaxf(v, __shfl_xor_sync(0xffffffffu, v, 1));
        v = fmaxf(v, __shfl_xor_sync(0xffffffffu, v, 2)); rmax10 = v;
        v = rmax11; v = fmaxf(v, __shfl_xor_sync(0xffffffffu, v, 1));
        v = fmaxf(v, __shfl_xor_sync(0xffffffffu, v, 2)); rmax11 = v;
    }
    if ((lane & 3) == 0) {
        const int rg = lane >> 2;
        float* rbuf = redbuf + wn * 128 + wm * 32;
        rbuf[rg]          = rmax00;
        rbuf[rg + 8]      = rmax01;
        rbuf[16 + rg]     = rmax10;
        rbuf[16 + rg + 8] = rmax11;
    }
    __syncthreads();

    if (tid < 128) {
        float m = fmaxf(redbuf[tid], redbuf[128 + tid]);
        #pragma unroll
        for (int o = 16; o; o >>= 1) {
            m += __shfl_xor_sync(0xffffffffu, m, o);
        }
        if (lane == 0) g_mscores[(rt * 4 + warp) * B + c] = m;
    }
}

// ---------------------------------------------------------------------------
// Kernel 3: epilogues (1 block, 64 threads)
// ---------------------------------------------------------------------------
__global__ void k_final(float* __restrict__ out) {
    __shared__ float s_sv[B];
    __shared__ float s_mv[B];
    const int b = threadIdx.x;

    float row[B];
    #pragma unroll 8
    for (int c = 0; c < B; c++) {
        float s = 0.0f;
        #pragma unroll
        for (int kc = 0; kc < KSPLIT; kc++) {
            s += g_part[(kc * B + b) * B + c];
        }
        row[c] = s;
    }
    float mx = -3.0e38f;
    for (int c = 0; c < B; c++) mx = fmaxf(mx, row[c]);
    float se = 0.0f;
    for (int c = 0; c < B; c++) se += expf(row[c] - mx);
    s_sv[b] = mx + logf(se) - row[b];

    const float* mrow = g_mscores + b * B;
    float pos = mrow[b];
    float neg = -3.0e38f;
    for (int c = 0; c < B; c++) {
        float v = mrow[c] - (c == b ? NEG_MASK : 0.0f);
        neg = fmaxf(neg, v);
    }
    float x = neg - pos;
    s_mv[b] = fmaxf(x, 0.0f) + log1pf(expf(-fabsf(x)));

    __syncthreads();
    if (b == 0) {
        float sv = 0.0f, mv = 0.0f;
        for (int i = 0; i < B; i++) { sv += s_sv[i]; mv += s_mv[i]; }
        out[0] = ALPHA * sv + (1.0f - ALPHA) * (mv / B);
    }
}

// ---------------------------------------------------------------------------
extern "C" void kernel_launch(void* const* d_in, const int* in_sizes, int n_in,
                              void* d_out, int out_size) {
    const float* q_single = (const float*)d_in[0];  // [64, 1024]
    const float* d_single = (const float*)d_in[1];  // [64, 1024]
    const float* q_multi  = (const float*)d_in[2];  // [64, 32, 128]
    const float* d_multi  = (const float*)d_in[3];  // [64, 1024, 128]
    float* out = (float*)d_out;

    cudaFuncSetAttribute(k_multi_tc, cudaFuncAttributeMaxDynamicSharedMemorySize,
                         SMEM_TOT);

    k_conv<<<(NDM4 + NQM4 + 255) / 256, 256>>>((const float4*)d_multi,
                                               (const float4*)q_multi);
    k_single<<<dim3(B, KSPLIT), 256>>>(q_single, d_single);
    k_multi_tc<<<dim3(16, B), 256, SMEM_TOT>>>();
    k_final<<<1, B>>>(out);
}

// round 5
// speedup vs baseline: 1.0757x; 1.0757x over previous
#include <cuda_runtime.h>
#include <cuda_bf16.h>
#include <cstdint>
#include <math.h>

#define B        64
#define DV       1024
#define NQ       32
#define NS       1024
#define D        128
#define NEG_MASK 1000000.0f
#define ALPHA    0.5f
#define LDP      136            // padded smem row stride (bf16 elems) -> 272 B
#define ROWB     272            // bytes per smem row

// dynamic smem arena (bytes)
#define OFF_AS   0
#define OFF_B0   34816
#define OFF_B1   69632
#define OFF_RED  104448
#define SMEM_TOT 105472

#define KSPLIT   8

__device__ float g_part[KSPLIT * B * B];        // k-split single-vector partials
__device__ float g_mscores[B * B];              // multi-vector scores
__device__ __nv_bfloat162 g_dmb[B * NS * D / 2]; // d_multi in bf16 (16 MB)
__device__ __nv_bfloat162 g_qmb[B * NQ * D / 2]; // q_multi in bf16 (512 KB)

// ---------------------------------------------------------------------------
// PTX helpers
// ---------------------------------------------------------------------------
__device__ __forceinline__ void ldsm_x4(unsigned int* r, unsigned int addr) {
    asm volatile("ldmatrix.sync.aligned.m8n8.x4.shared.b16 {%0,%1,%2,%3}, [%4];"
                 : "=r"(r[0]), "=r"(r[1]), "=r"(r[2]), "=r"(r[3]) : "r"(addr));
}
__device__ __forceinline__ void mma_16816(float* c, const unsigned int* a,
                                          const unsigned int* b) {
    asm volatile("mma.sync.aligned.m16n8k16.row.col.f32.bf16.bf16.f32 "
                 "{%0,%1,%2,%3}, {%4,%5,%6,%7}, {%8,%9}, {%0,%1,%2,%3};"
                 : "+f"(c[0]), "+f"(c[1]), "+f"(c[2]), "+f"(c[3])
                 : "r"(a[0]), "r"(a[1]), "r"(a[2]), "r"(a[3]), "r"(b[0]), "r"(b[1]));
}
__device__ __forceinline__ void cp_async16(unsigned int saddr, const void* gptr) {
    size_t g = __cvta_generic_to_global(gptr);
    asm volatile("cp.async.cg.shared.global [%0], [%1], 16;" :: "r"(saddr), "l"(g));
}
__device__ __forceinline__ void cp_commit() {
    asm volatile("cp.async.commit_group;");
}
template <int N> __device__ __forceinline__ void cp_wait() {
    asm volatile("cp.async.wait_group %0;" :: "n"(N));
}

// ---------------------------------------------------------------------------
// Kernel 0: fp32 -> bf16 conversion of q_multi and d_multi (one pass)
// ---------------------------------------------------------------------------
#define NDM4 (B * NS * D / 4)   // 2097152 float4s of d_multi
#define NQM4 (B * NQ * D / 4)   // 65536 float4s of q_multi
__global__ void __launch_bounds__(256) k_conv(const float4* __restrict__ dm,
                                              const float4* __restrict__ qm) {
    int i = blockIdx.x * 256 + threadIdx.x;
    if (i < NDM4) {
        float4 v = dm[i];
        g_dmb[i * 2]     = __floats2bfloat162_rn(v.x, v.y);
        g_dmb[i * 2 + 1] = __floats2bfloat162_rn(v.z, v.w);
    } else {
        int j = i - NDM4;
        if (j < NQM4) {
            float4 v = qm[j];
            g_qmb[j * 2]     = __floats2bfloat162_rn(v.x, v.y);
            g_qmb[j * 2 + 1] = __floats2bfloat162_rn(v.z, v.w);
        }
    }
}

// ---------------------------------------------------------------------------
// Kernel 1: single-vector partial scores, k-split by 8 (chunks of 128).
// ---------------------------------------------------------------------------
__global__ void __launch_bounds__(256) k_single(const float* __restrict__ q,
                                                const float* __restrict__ d) {
    __shared__ float qs[128];
    const int b   = blockIdx.x;
    const int kc  = blockIdx.y;
    const int tid = threadIdx.x;
    if (tid < 128) qs[tid] = q[b * DV + kc * 128 + tid];
    __syncthreads();

    const int w    = tid >> 5;
    const int lane = tid & 31;
    #pragma unroll
    for (int cc = 0; cc < 8; cc++) {
        const int c = cc * 8 + w;
        const float* dv = d + c * DV + kc * 128;
        float p = 0.0f;
        #pragma unroll
        for (int i = 0; i < 4; i++) {
            p += qs[lane + i * 32] * dv[lane + i * 32];
        }
        #pragma unroll
        for (int o = 16; o; o >>= 1) {
            p += __shfl_xor_sync(0xffffffffu, p, o);
        }
        if (lane == 0) g_part[(kc * B + b) * B + c] = p;
    }
}

// ---------------------------------------------------------------------------
// Kernel 2: multi-vector late interaction, bf16 mma.sync, cp.async pipeline.
// grid (16 rt, 64 c); 8 warps as 4(m32) x 2(n64) per 128-wide s-tile.
// ---------------------------------------------------------------------------
__global__ void __launch_bounds__(256, 2) k_multi_tc() {
    extern __shared__ char smem_raw[];
    const unsigned int sbase = (unsigned int)__cvta_generic_to_shared(smem_raw);
    const unsigned int sA  = sbase + OFF_AS;
    const unsigned int sB0 = sbase + OFF_B0;
    const unsigned int sB1 = sbase + OFF_B1;
    float* redbuf = (float*)(smem_raw + OFF_RED);   // [2][128]

    const int rt   = blockIdx.x;   // 0..15
    const int c    = blockIdx.y;   // 0..63
    const int tid  = threadIdx.x;
    const int lane = tid & 31;
    const int warp = tid >> 5;
    const int wm   = warp >> 1;    // 0..3
    const int wn   = warp & 1;     // 0..1

    const __nv_bfloat16* Aq = (const __nv_bfloat16*)g_qmb + (size_t)rt * 128 * D;
    const __nv_bfloat16* Dq = (const __nv_bfloat16*)g_dmb + (size_t)c * NS * D;

    // per-thread chunk coords (16 B chunks; 2048 chunks per 128x128 bf16 tile)
    const int ch  = tid & 15;          // chunk along k
    const int rb  = tid >> 4;          // base row (stride 16 over i)

    // issue A tile + B tile 0 as group 0
    #pragma unroll
    for (int i = 0; i < 8; i++) {
        int r = rb + i * 16;
        cp_async16(sA + r * ROWB + ch * 16, Aq + r * D + ch * 8);
    }
    #pragma unroll
    for (int i = 0; i < 8; i++) {
        int s = rb + i * 16;
        cp_async16(sB0 + s * ROWB + ch * 16, Dq + s * D + ch * 8);
    }
    cp_commit();

    // ldmatrix lane addresses
    const int arow = lane & 15;
    const int acol = (lane >> 4) * 8;
    const unsigned int a_addr0 = sA + (wm * 32 + arow) * ROWB + acol * 2;
    const unsigned int a_addr1 = a_addr0 + 16 * ROWB;

    const int g = lane >> 3;           // 0..3
    const unsigned int b_lane_off =
        (unsigned int)((wn * 64 + (g >> 1) * 8 + (lane & 7)) * ROWB + (g & 1) * 16);

    float rmax00 = -3.0e38f, rmax01 = -3.0e38f;
    float rmax10 = -3.0e38f, rmax11 = -3.0e38f;

    for (int st = 0; st < 8; st++) {
        // prefetch next B tile into the other buffer
        if (st < 7) {
            const unsigned int dstB = ((st + 1) & 1) ? sB1 : sB0;
            const __nv_bfloat16* src = Dq + (size_t)(st + 1) * 128 * D;
            #pragma unroll
            for (int i = 0; i < 8; i++) {
                int s = rb + i * 16;
                cp_async16(dstB + s * ROWB + ch * 16, src + s * D + ch * 8);
            }
            cp_commit();
            cp_wait<1>();
        } else {
            cp_wait<0>();
        }
        __syncthreads();

        const unsigned int bufB = (st & 1) ? sB1 : sB0;
        const unsigned int b_base = bufB + b_lane_off;

        float acc[2][8][4];
        #pragma unroll
        for (int mt = 0; mt < 2; mt++) {
            #pragma unroll
            for (int nt = 0; nt < 8; nt++) {
                acc[mt][nt][0] = 0.0f; acc[mt][nt][1] = 0.0f;
                acc[mt][nt][2] = 0.0f; acc[mt][nt][3] = 0.0f;
            }
        }

        #pragma unroll
        for (int kt = 0; kt < 8; kt++) {
            unsigned int a0[4], a1[4];
            ldsm_x4(a0, a_addr0 + kt * 32);
            ldsm_x4(a1, a_addr1 + kt * 32);
            #pragma unroll
            for (int p = 0; p < 4; p++) {
                unsigned int bfr[4];           // {b0,b1} for nt=2p, {b0,b1} for nt=2p+1
                ldsm_x4(bfr, b_base + p * (16 * ROWB) + kt * 32);
                mma_16816(acc[0][2 * p],     a0, bfr);
                mma_16816(acc[1][2 * p],     a1, bfr);
                mma_16816(acc[0][2 * p + 1], a0, bfr + 2);
                mma_16816(acc[1][2 * p + 1], a1, bfr + 2);
            }
        }

        // fold s-tile into running per-row maxima
        float m0 = -3.0e38f, m1 = -3.0e38f, m2 = -3.0e38f, m3 = -3.0e38f;
        #pragma unroll
        for (int nt = 0; nt < 8; nt++) {
            m0 = fmaxf(m0, fmaxf(acc[0][nt][0], acc[0][nt][1]));
            m1 = fmaxf(m1, fmaxf(acc[0][nt][2], acc[0][nt][3]));
            m2 = fmaxf(m2, fmaxf(acc[1][nt][0], acc[1][nt][1]));
            m3 = fmaxf(m3, fmaxf(acc[1][nt][2], acc[1][nt][3]));
        }
        rmax00 = fmaxf(rmax00, m0); rmax01 = fmaxf(rmax01, m1);
        rmax10 = fmaxf(rmax10, m2); rmax11 = fmaxf(rmax11, m3);

        __syncthreads();   // compute done before this buffer is refilled (st+2)
    }

    // cross-lane max: lanes l^1, l^2 hold other columns of the same row
    {
        float v;
        v = rmax00; v = fmaxf(v, __shfl_xor_sync(0xffffffffu, v, 1));
        v = fmaxf(v, __shfl_xor_sync(0xffffffffu, v, 2)); rmax00 = v;
        v = rmax01; v = fmaxf(v, __shfl_xor_sync(0xffffffffu, v, 1));
        v = fmaxf(v, __shfl_xor_sync(0xffffffffu, v, 2)); rmax01 = v;
        v = rmax10; v = fmaxf(v, __shfl_xor_sync(0xffffffffu, v, 1));
        v = fmaxf(v, __shfl_xor_sync(0xffffffffu, v, 2)); rmax10 = v;
        v = rmax11; v = fmaxf(v, __shfl_xor_sync(0xffffffffu, v, 1));
        v = fmaxf(v, __shfl_xor_sync(0xffffffffu, v, 2)); rmax11 = v;
    }
    if ((lane & 3) == 0) {
        const int rg = lane >> 2;
        float* rbuf = redbuf + wn * 128 + wm * 32;
        rbuf[rg]          = rmax00;
        rbuf[rg + 8]      = rmax01;
        rbuf[16 + rg]     = rmax10;
        rbuf[16 + rg + 8] = rmax11;
    }
    __syncthreads();

    if (tid < 128) {
        float m = fmaxf(redbuf[tid], redbuf[128 + tid]);
        #pragma unroll
        for (int o = 16; o; o >>= 1) {
            m += __shfl_xor_sync(0xffffffffu, m, o);
        }
        if (lane == 0) g_mscores[(rt * 4 + warp) * B + c] = m;
    }
}

// ---------------------------------------------------------------------------
// Kernel 3: epilogues, lane-parallel (256 threads, warp per 8 b's, no spills).
// ---------------------------------------------------------------------------
__global__ void __launch_bounds__(256) k_final(float* __restrict__ out) {
    __shared__ float s_sv[8];
    __shared__ float s_mv[8];
    const int warp = threadIdx.x >> 5;
    const int lane = threadIdx.x & 31;

    float sv = 0.0f, mv = 0.0f;
    #pragma unroll
    for (int i = 0; i < 8; i++) {
        const int b = warp * 8 + i;

        // ---- single-vector CE term: lane l owns columns l and l+32 ----
        float v0 = 0.0f, v1 = 0.0f;
        #pragma unroll
        for (int kc = 0; kc < KSPLIT; kc++) {
            const float* p = g_part + (kc * B + b) * B;
            v0 += p[lane];
            v1 += p[lane + 32];
        }
        float mx = fmaxf(v0, v1);
        #pragma unroll
        for (int o = 16; o; o >>= 1) {
            mx = fmaxf(mx, __shfl_xor_sync(0xffffffffu, mx, o));
        }
        float se = expf(v0 - mx) + expf(v1 - mx);
        #pragma unroll
        for (int o = 16; o; o >>= 1) {
            se += __shfl_xor_sync(0xffffffffu, se, o);
        }
        float diag = __shfl_sync(0xffffffffu, (b < 32) ? v0 : v1, b & 31);
        sv += mx + logf(se) - diag;

        // ---- multi-vector margin term ----
        const float* mrow = g_mscores + b * B;
        float m0 = mrow[lane];
        float m1 = mrow[lane + 32];
        float pos = __shfl_sync(0xffffffffu, (b < 32) ? m0 : m1, b & 31);
        float n0 = (lane == b)      ? -3.0e38f : m0;
        float n1 = (lane + 32 == b) ? -3.0e38f : m1;
        float neg = fmaxf(n0, n1);
        #pragma unroll
        for (int o = 16; o; o >>= 1) {
            neg = fmaxf(neg, __shfl_xor_sync(0xffffffffu, neg, o));
        }
        float x = neg - pos;
        mv += fmaxf(x, 0.0f) + log1pf(expf(-fabsf(x)));
    }

    if (lane == 0) { s_sv[warp] = sv; s_mv[warp] = mv; }
    __syncthreads();
    if (threadIdx.x == 0) {
        float SV = 0.0f, MV = 0.0f;
        #pragma unroll
        for (int i = 0; i < 8; i++) { SV += s_sv[i]; MV += s_mv[i]; }
        out[0] = ALPHA * SV + (1.0f - ALPHA) * (MV / B);
    }
}

// ---------------------------------------------------------------------------
extern "C" void kernel_launch(void* const* d_in, const int* in_sizes, int n_in,
                              void* d_out, int out_size) {
    const float* q_single = (const float*)d_in[0];  // [64, 1024]
    const float* d_single = (const float*)d_in[1];  // [64, 1024]
    const float* q_multi  = (const float*)d_in[2];  // [64, 32, 128]
    const float* d_multi  = (const float*)d_in[3];  // [64, 1024, 128]
    float* out = (float*)d_out;

    cudaFuncSetAttribute(k_multi_tc, cudaFuncAttributeMaxDynamicSharedMemorySize,
                         SMEM_TOT);

    k_conv<<<(NDM4 + NQM4 + 255) / 256, 256>>>((const float4*)d_multi,
                                               (const float4*)q_multi);
    k_single<<<dim3(B, KSPLIT), 256>>>(q_single, d_single);
    k_multi_tc<<<dim3(16, B), 256, SMEM_TOT>>>();
    k_final<<<1, 256>>>(out);
}

// round 6
// speedup vs baseline: 1.1113x; 1.0331x over previous
#include <cuda_runtime.h>
#include <cuda_bf16.h>
#include <cstdint>
#include <math.h>

#define B        64
#define DV       1024
#define NQ       32
#define NS       1024
#define D        128
#define NEG_MASK 1000000.0f
#define ALPHA    0.5f
#define ROWB     144            // 128 B fp8 row + 16 B pad (conflict-free ldmatrix)

// dynamic smem arena (bytes)
#define OFF_AS   0
#define OFF_B0   18432          // 128*144
#define OFF_B1   36864
#define OFF_RED  55296
#define SMEM_TOT 56320

#define KSPLIT   8

__device__ float g_part[KSPLIT * B * B];        // k-split single-vector partials
__device__ float g_mscores[B * B];              // multi-vector scores
__device__ unsigned char g_dm8[B * NS * D];     // d_multi in e4m3 (8 MB)
__device__ unsigned char g_qm8[B * NQ * D];     // q_multi in e4m3 (256 KB)

// ---------------------------------------------------------------------------
// PTX helpers
// ---------------------------------------------------------------------------
__device__ __forceinline__ void ldsm_x4(unsigned int* r, unsigned int addr) {
    asm volatile("ldmatrix.sync.aligned.m8n8.x4.shared.b16 {%0,%1,%2,%3}, [%4];"
                 : "=r"(r[0]), "=r"(r[1]), "=r"(r[2]), "=r"(r[3]) : "r"(addr));
}
__device__ __forceinline__ void mma_fp8(float* c, const unsigned int* a,
                                        const unsigned int* b) {
    asm volatile("mma.sync.aligned.m16n8k32.row.col.f32.e4m3.e4m3.f32 "
                 "{%0,%1,%2,%3}, {%4,%5,%6,%7}, {%8,%9}, {%0,%1,%2,%3};"
                 : "+f"(c[0]), "+f"(c[1]), "+f"(c[2]), "+f"(c[3])
                 : "r"(a[0]), "r"(a[1]), "r"(a[2]), "r"(a[3]), "r"(b[0]), "r"(b[1]));
}
__device__ __forceinline__ void cp_async16(unsigned int saddr, const void* gptr) {
    size_t g = __cvta_generic_to_global(gptr);
    asm volatile("cp.async.cg.shared.global [%0], [%1], 16;" :: "r"(saddr), "l"(g));
}
__device__ __forceinline__ void cp_commit() {
    asm volatile("cp.async.commit_group;");
}
template <int N> __device__ __forceinline__ void cp_wait() {
    asm volatile("cp.async.wait_group %0;" :: "n"(N));
}
__device__ __forceinline__ unsigned int pack_e4m3x4(float4 v) {
    unsigned short lo, hi;
    asm("cvt.rn.satfinite.e4m3x2.f32 %0, %1, %2;" : "=h"(lo) : "f"(v.y), "f"(v.x));
    asm("cvt.rn.satfinite.e4m3x2.f32 %0, %1, %2;" : "=h"(hi) : "f"(v.w), "f"(v.z));
    return (unsigned int)lo | ((unsigned int)hi << 16);
}

// ---------------------------------------------------------------------------
// Kernel 0: fp32 -> e4m3 conversion (one pass). Each thread: 16 floats -> 16 B.
// ---------------------------------------------------------------------------
#define NDM16 (B * NS * D / 16)   // 524288
#define NQM16 (B * NQ * D / 16)   // 16384
__global__ void __launch_bounds__(256) k_conv(const float4* __restrict__ dm,
                                              const float4* __restrict__ qm) {
    int i = blockIdx.x * 256 + threadIdx.x;
    if (i < NDM16) {
        uint4 o;
        o.x = pack_e4m3x4(dm[i * 4 + 0]);
        o.y = pack_e4m3x4(dm[i * 4 + 1]);
        o.z = pack_e4m3x4(dm[i * 4 + 2]);
        o.w = pack_e4m3x4(dm[i * 4 + 3]);
        ((uint4*)g_dm8)[i] = o;
    } else {
        int j = i - NDM16;
        if (j < NQM16) {
            uint4 o;
            o.x = pack_e4m3x4(qm[j * 4 + 0]);
            o.y = pack_e4m3x4(qm[j * 4 + 1]);
            o.z = pack_e4m3x4(qm[j * 4 + 2]);
            o.w = pack_e4m3x4(qm[j * 4 + 3]);
            ((uint4*)g_qm8)[j] = o;
        }
    }
}

// ---------------------------------------------------------------------------
// Kernel 1: single-vector partial scores, k-split by 8 (fp32, exact).
// ---------------------------------------------------------------------------
__global__ void __launch_bounds__(256) k_single(const float* __restrict__ q,
                                                const float* __restrict__ d) {
    __shared__ float qs[128];
    const int b   = blockIdx.x;
    const int kc  = blockIdx.y;
    const int tid = threadIdx.x;
    if (tid < 128) qs[tid] = q[b * DV + kc * 128 + tid];
    __syncthreads();

    const int w    = tid >> 5;
    const int lane = tid & 31;
    #pragma unroll
    for (int cc = 0; cc < 8; cc++) {
        const int c = cc * 8 + w;
        const float* dv = d + c * DV + kc * 128;
        float p = 0.0f;
        #pragma unroll
        for (int i = 0; i < 4; i++) {
            p += qs[lane + i * 32] * dv[lane + i * 32];
        }
        #pragma unroll
        for (int o = 16; o; o >>= 1) {
            p += __shfl_xor_sync(0xffffffffu, p, o);
        }
        if (lane == 0) g_part[(kc * B + b) * B + c] = p;
    }
}

// ---------------------------------------------------------------------------
// Kernel 2: multi-vector late interaction, e4m3 mma.sync m16n8k32.
// grid (16 rt, 64 c); 8 warps as 4(m32) x 2(n64) per 128-wide s-tile.
// ---------------------------------------------------------------------------
__global__ void __launch_bounds__(256, 2) k_multi_tc() {
    extern __shared__ char smem_raw[];
    const unsigned int sbase = (unsigned int)__cvta_generic_to_shared(smem_raw);
    const unsigned int sA  = sbase + OFF_AS;
    const unsigned int sB0 = sbase + OFF_B0;
    const unsigned int sB1 = sbase + OFF_B1;
    float* redbuf = (float*)(smem_raw + OFF_RED);   // [2][128]

    const int rt   = blockIdx.x;   // 0..15
    const int c    = blockIdx.y;   // 0..63
    const int tid  = threadIdx.x;
    const int lane = tid & 31;
    const int warp = tid >> 5;
    const int wm   = warp >> 1;    // 0..3
    const int wn   = warp & 1;     // 0..1

    const unsigned char* Aq = g_qm8 + (size_t)rt * 128 * D;
    const unsigned char* Dq = g_dm8 + (size_t)c * NS * D;

    // per-thread chunk coords: 16B chunks, 8 per 128B row; 1024 chunks per tile
    const int ch = tid & 7;            // chunk along k
    const int rb = tid >> 3;           // base row 0..31 (stride 32)

    // issue A tile + B tile 0 as group 0
    #pragma unroll
    for (int i = 0; i < 4; i++) {
        int r = rb + i * 32;
        cp_async16(sA + r * ROWB + ch * 16, Aq + r * D + ch * 16);
    }
    #pragma unroll
    for (int i = 0; i < 4; i++) {
        int s = rb + i * 32;
        cp_async16(sB0 + s * ROWB + ch * 16, Dq + s * D + ch * 16);
    }
    cp_commit();

    // ldmatrix lane addresses (fp8 m16n8k32 fragments)
    const unsigned int a_addr0 =
        sA + (wm * 32 + (lane & 15)) * ROWB + (lane >> 4) * 16;
    const unsigned int a_addr1 = a_addr0 + 16 * ROWB;

    const unsigned int b_lane_off =
        (unsigned int)((wn * 64 + ((lane >> 4) & 1) * 8 + (lane & 7)) * ROWB +
                       ((lane >> 3) & 1) * 16);

    float rmax00 = -3.0e38f, rmax01 = -3.0e38f;
    float rmax10 = -3.0e38f, rmax11 = -3.0e38f;

    for (int st = 0; st < 8; st++) {
        if (st < 7) {
            const unsigned int dstB = ((st + 1) & 1) ? sB1 : sB0;
            const unsigned char* src = Dq + (size_t)(st + 1) * 128 * D;
            #pragma unroll
            for (int i = 0; i < 4; i++) {
                int s = rb + i * 32;
                cp_async16(dstB + s * ROWB + ch * 16, src + s * D + ch * 16);
            }
            cp_commit();
            cp_wait<1>();
        } else {
            cp_wait<0>();
        }
        __syncthreads();

        const unsigned int bufB = (st & 1) ? sB1 : sB0;
        const unsigned int b_base = bufB + b_lane_off;

        float acc[2][8][4];
        #pragma unroll
        for (int mt = 0; mt < 2; mt++) {
            #pragma unroll
            for (int nt = 0; nt < 8; nt++) {
                acc[mt][nt][0] = 0.0f; acc[mt][nt][1] = 0.0f;
                acc[mt][nt][2] = 0.0f; acc[mt][nt][3] = 0.0f;
            }
        }

        #pragma unroll
        for (int kt = 0; kt < 4; kt++) {           // 4 k-steps of 32 bytes
            unsigned int a0[4], a1[4];
            ldsm_x4(a0, a_addr0 + kt * 32);
            ldsm_x4(a1, a_addr1 + kt * 32);
            #pragma unroll
            for (int p = 0; p < 4; p++) {
                unsigned int bfr[4];               // b-frags for nt=2p, 2p+1
                ldsm_x4(bfr, b_base + p * (16 * ROWB) + kt * 32);
                mma_fp8(acc[0][2 * p],     a0, bfr);
                mma_fp8(acc[1][2 * p],     a1, bfr);
                mma_fp8(acc[0][2 * p + 1], a0, bfr + 2);
                mma_fp8(acc[1][2 * p + 1], a1, bfr + 2);
            }
        }

        // fold s-tile into running per-row maxima
        float m0 = -3.0e38f, m1 = -3.0e38f, m2 = -3.0e38f, m3 = -3.0e38f;
        #pragma unroll
        for (int nt = 0; nt < 8; nt++) {
            m0 = fmaxf(m0, fmaxf(acc[0][nt][0], acc[0][nt][1]));
            m1 = fmaxf(m1, fmaxf(acc[0][nt][2], acc[0][nt][3]));
            m2 = fmaxf(m2, fmaxf(acc[1][nt][0], acc[1][nt][1]));
            m3 = fmaxf(m3, fmaxf(acc[1][nt][2], acc[1][nt][3]));
        }
        rmax00 = fmaxf(rmax00, m0); rmax01 = fmaxf(rmax01, m1);
        rmax10 = fmaxf(rmax10, m2); rmax11 = fmaxf(rmax11, m3);

        __syncthreads();   // compute done before this buffer is refilled
    }

    // cross-lane max: lanes l^1, l^2 hold other columns of the same row
    {
        float v;
        v = rmax00; v = fmaxf(v, __shfl_xor_sync(0xffffffffu, v, 1));
        v = fmaxf(v, __shfl_xor_sync(0xffffffffu, v, 2)); rmax00 = v;
        v = rmax01; v = fmaxf(v, __shfl_xor_sync(0xffffffffu, v, 1));
        v = fmaxf(v, __shfl_xor_sync(0xffffffffu, v, 2)); rmax01 = v;
        v = rmax10; v = fmaxf(v, __shfl_xor_sync(0xffffffffu, v, 1));
        v = fmaxf(v, __shfl_xor_sync(0xffffffffu, v, 2)); rmax10 = v;
        v = rmax11; v = fmaxf(v, __shfl_xor_sync(0xffffffffu, v, 1));
        v = fmaxf(v, __shfl_xor_sync(0xffffffffu, v, 2)); rmax11 = v;
    }
    if ((lane & 3) == 0) {
        const int rg = lane >> 2;
        float* rbuf = redbuf + wn * 128 + wm * 32;
        rbuf[rg]          = rmax00;
        rbuf[rg + 8]      = rmax01;
        rbuf[16 + rg]     = rmax10;
        rbuf[16 + rg + 8] = rmax11;
    }
    __syncthreads();

    if (tid < 128) {
        float m = fmaxf(redbuf[tid], redbuf[128 + tid]);
        #pragma unroll
        for (int o = 16; o; o >>= 1) {
            m += __shfl_xor_sync(0xffffffffu, m, o);
        }
        if (lane == 0) g_mscores[(rt * 4 + warp) * B + c] = m;
    }
}

// ---------------------------------------------------------------------------
// Kernel 3: epilogues. 1024 threads, 32 warps, warp w handles b = w, w+32.
// ---------------------------------------------------------------------------
__global__ void __launch_bounds__(1024) k_final(float* __restrict__ out) {
    __shared__ float s_sv[32];
    __shared__ float s_mv[32];
    const int warp = threadIdx.x >> 5;
    const int lane = threadIdx.x & 31;

    float sv = 0.0f, mv = 0.0f;
    #pragma unroll
    for (int i = 0; i < 2; i++) {
        const int b = warp + i * 32;

        // ---- single-vector CE term: lane l owns columns l and l+32 ----
        float v0 = 0.0f, v1 = 0.0f;
        #pragma unroll
        for (int kc = 0; kc < KSPLIT; kc++) {
            const float* p = g_part + (kc * B + b) * B;
            v0 += p[lane];
            v1 += p[lane + 32];
        }
        float mx = fmaxf(v0, v1);
        #pragma unroll
        for (int o = 16; o; o >>= 1) {
            mx = fmaxf(mx, __shfl_xor_sync(0xffffffffu, mx, o));
        }
        float se = expf(v0 - mx) + expf(v1 - mx);
        #pragma unroll
        for (int o = 16; o; o >>= 1) {
            se += __shfl_xor_sync(0xffffffffu, se, o);
        }
        float diag = __shfl_sync(0xffffffffu, (b < 32) ? v0 : v1, b & 31);
        sv += mx + logf(se) - diag;

        // ---- multi-vector margin term ----
        const float* mrow = g_mscores + b * B;
        float m0 = mrow[lane];
        float m1 = mrow[lane + 32];
        float pos = __shfl_sync(0xffffffffu, (b < 32) ? m0 : m1, b & 31);
        float n0 = (lane == b)      ? -3.0e38f : m0;
        float n1 = (lane + 32 == b) ? -3.0e38f : m1;
        float neg = fmaxf(n0, n1);
        #pragma unroll
        for (int o = 16; o; o >>= 1) {
            neg = fmaxf(neg, __shfl_xor_sync(0xffffffffu, neg, o));
        }
        float x = neg - pos;
        mv += fmaxf(x, 0.0f) + log1pf(expf(-fabsf(x)));
    }

    if (lane == 0) { s_sv[warp] = sv; s_mv[warp] = mv; }
    __syncthreads();
    if (warp == 0) {
        float SV = s_sv[lane];
        float MV = s_mv[lane];
        #pragma unroll
        for (int o = 16; o; o >>= 1) {
            SV += __shfl_xor_sync(0xffffffffu, SV, o);
            MV += __shfl_xor_sync(0xffffffffu, MV, o);
        }
        if (lane == 0) out[0] = ALPHA * SV + (1.0f - ALPHA) * (MV / B);
    }
}

// ---------------------------------------------------------------------------
extern "C" void kernel_launch(void* const* d_in, const int* in_sizes, int n_in,
                              void* d_out, int out_size) {
    const float* q_single = (const float*)d_in[0];  // [64, 1024]
    const float* d_single = (const float*)d_in[1];  // [64, 1024]
    const float* q_multi  = (const float*)d_in[2];  // [64, 32, 128]
    const float* d_multi  = (const float*)d_in[3];  // [64, 1024, 128]
    float* out = (float*)d_out;

    cudaFuncSetAttribute(k_multi_tc, cudaFuncAttributeMaxDynamicSharedMemorySize,
                         SMEM_TOT);

    k_conv<<<(NDM16 + NQM16 + 255) / 256, 256>>>((const float4*)d_multi,
                                                 (const float4*)q_multi);
    k_single<<<dim3(B, KSPLIT), 256>>>(q_single, d_single);
    k_multi_tc<<<dim3(16, B), 256, SMEM_TOT>>>();
    k_final<<<1, 1024>>>(out);
}

// round 9
// speedup vs baseline: 1.2116x; 1.0903x over previous
#include <cuda_runtime.h>
#include <cuda_bf16.h>
#include <cstdint>
#include <math.h>

#define B        64
#define DV       1024
#define NQ       32
#define NS       1024
#define D        128
#define NEG_MASK 1000000.0f
#define ALPHA    0.5f
#define ROWB     272            // bytes per smem row (136 bf16, conflict-free)

// dynamic smem arena (bytes) for k_multi
#define OFF_AS   0
#define OFF_B0   34816
#define OFF_B1   69632
#define OFF_RED  104448
#define SMEM_TOT 105472

#define KSPLIT   8
#define NDM4     (B * NS * D / 4)       // 2097152 float4s of d_multi
#define NQM4     (B * NQ * D / 4)       // 65536 float4s of q_multi
#define NCONV    ((NDM4 + NQM4 + 255) / 256)   // conv blocks
#define NSING    (B * KSPLIT)                  // k_single blocks

__device__ float g_part[KSPLIT * B * B];         // k-split single-vector partials
__device__ float g_mscores[B * B];               // multi-vector scores
__device__ __nv_bfloat162 g_dmb[B * NS * D / 2]; // d_multi bf16 (16 MB)
__device__ __nv_bfloat162 g_qmb[B * NQ * D / 2]; // q_multi bf16 (512 KB)

// ---------------------------------------------------------------------------
// PTX helpers
// ---------------------------------------------------------------------------
__device__ __forceinline__ void ldsm_x4(unsigned int* r, unsigned int addr) {
    asm volatile("ldmatrix.sync.aligned.m8n8.x4.shared.b16 {%0,%1,%2,%3}, [%4];"
                 : "=r"(r[0]), "=r"(r[1]), "=r"(r[2]), "=r"(r[3]) : "r"(addr));
}
__device__ __forceinline__ void mma_16816(float* c, const unsigned int* a,
                                          const unsigned int* b) {
    asm volatile("mma.sync.aligned.m16n8k16.row.col.f32.bf16.bf16.f32 "
                 "{%0,%1,%2,%3}, {%4,%5,%6,%7}, {%8,%9}, {%0,%1,%2,%3};"
                 : "+f"(c[0]), "+f"(c[1]), "+f"(c[2]), "+f"(c[3])
                 : "r"(a[0]), "r"(a[1]), "r"(a[2]), "r"(a[3]), "r"(b[0]), "r"(b[1]));
}
__device__ __forceinline__ void cp_async16(unsigned int saddr, const void* gptr) {
    size_t g = __cvta_generic_to_global(gptr);
    asm volatile("cp.async.cg.shared.global [%0], [%1], 16;" :: "r"(saddr), "l"(g));
}
__device__ __forceinline__ void cp_commit() {
    asm volatile("cp.async.commit_group;");
}
template <int N> __device__ __forceinline__ void cp_wait() {
    asm volatile("cp.async.wait_group %0;" :: "n"(N));
}

// ---------------------------------------------------------------------------
// Kernel A (fused): blocks [0, NCONV) convert fp32->bf16; blocks
// [NCONV, NCONV+NSING) compute single-vector k-split partial scores.
// ---------------------------------------------------------------------------
__global__ void __launch_bounds__(256) k_prep(const float4* __restrict__ dm,
                                              const float4* __restrict__ qm,
                                              const float* __restrict__ q,
                                              const float* __restrict__ d) {
    const int bx  = blockIdx.x;
    const int tid = threadIdx.x;

    if (bx < NCONV) {
        int i = bx * 256 + tid;
        if (i < NDM4) {
            float4 v = dm[i];
            g_dmb[i * 2]     = __floats2bfloat162_rn(v.x, v.y);
            g_dmb[i * 2 + 1] = __floats2bfloat162_rn(v.z, v.w);
        } else {
            int j = i - NDM4;
            if (j < NQM4) {
                float4 v = qm[j];
                g_qmb[j * 2]     = __floats2bfloat162_rn(v.x, v.y);
                g_qmb[j * 2 + 1] = __floats2bfloat162_rn(v.z, v.w);
            }
        }
        return;
    }

    // ---- single-vector partials ----
    __shared__ float qs[128];
    const int idx = bx - NCONV;
    const int b   = idx & (B - 1);
    const int kc  = idx >> 6;
    if (tid < 128) qs[tid] = q[b * DV + kc * 128 + tid];
    __syncthreads();

    const int w    = tid >> 5;
    const int lane = tid & 31;
    #pragma unroll
    for (int cc = 0; cc < 8; cc++) {
        const int c = cc * 8 + w;
        const float* dv = d + c * DV + kc * 128;
        float p = 0.0f;
        #pragma unroll
        for (int i = 0; i < 4; i++) {
            p += qs[lane + i * 32] * dv[lane + i * 32];
        }
        #pragma unroll
        for (int o = 16; o; o >>= 1) {
            p += __shfl_xor_sync(0xffffffffu, p, o);
        }
        if (lane == 0) g_part[(kc * B + b) * B + c] = p;
    }
}

// ---------------------------------------------------------------------------
// Kernel 2: multi-vector late interaction, bf16 mma.sync, cp.async pipeline.
// grid (16 rt, 64 c); 8 warps as 4(m32) x 2(n64) per 128-wide s-tile.
// (R5 configuration — measured best on this toolchain.)
// ---------------------------------------------------------------------------
__global__ void __launch_bounds__(256, 2) k_multi_tc() {
    extern __shared__ char smem_raw[];
    const unsigned int sbase = (unsigned int)__cvta_generic_to_shared(smem_raw);
    const unsigned int sA  = sbase + OFF_AS;
    const unsigned int sB0 = sbase + OFF_B0;
    const unsigned int sB1 = sbase + OFF_B1;
    float* redbuf = (float*)(smem_raw + OFF_RED);   // [2][128]

    const int rt   = blockIdx.x;   // 0..15
    const int c    = blockIdx.y;   // 0..63
    const int tid  = threadIdx.x;
    const int lane = tid & 31;
    const int warp = tid >> 5;
    const int wm   = warp >> 1;    // 0..3
    const int wn   = warp & 1;     // 0..1

    const __nv_bfloat16* Aq = (const __nv_bfloat16*)g_qmb + (size_t)rt * 128 * D;
    const __nv_bfloat16* Dq = (const __nv_bfloat16*)g_dmb + (size_t)c * NS * D;

    // per-thread chunk coords (16 B chunks; 2048 chunks per 128x128 bf16 tile)
    const int ch = tid & 15;           // chunk along k
    const int rb = tid >> 4;           // base row (stride 16 over i)

    // issue A tile + B tile 0 as group 0
    #pragma unroll
    for (int i = 0; i < 8; i++) {
        int r = rb + i * 16;
        cp_async16(sA + r * ROWB + ch * 16, Aq + r * D + ch * 8);
    }
    #pragma unroll
    for (int i = 0; i < 8; i++) {
        int s = rb + i * 16;
        cp_async16(sB0 + s * ROWB + ch * 16, Dq + s * D + ch * 8);
    }
    cp_commit();

    // ldmatrix lane addresses
    const int arow = lane & 15;
    const int acol = (lane >> 4) * 8;
    const unsigned int a_addr0 = sA + (wm * 32 + arow) * ROWB + acol * 2;
    const unsigned int a_addr1 = a_addr0 + 16 * ROWB;

    const int g = lane >> 3;           // 0..3
    const unsigned int b_lane_off =
        (unsigned int)((wn * 64 + (g >> 1) * 8 + (lane & 7)) * ROWB + (g & 1) * 16);

    float rmax00 = -3.0e38f, rmax01 = -3.0e38f;
    float rmax10 = -3.0e38f, rmax11 = -3.0e38f;

    for (int st = 0; st < 8; st++) {
        if (st < 7) {
            const unsigned int dstB = ((st + 1) & 1) ? sB1 : sB0;
            const __nv_bfloat16* src = Dq + (size_t)(st + 1) * 128 * D;
            #pragma unroll
            for (int i = 0; i < 8; i++) {
                int s = rb + i * 16;
                cp_async16(dstB + s * ROWB + ch * 16, src + s * D + ch * 8);
            }
            cp_commit();
            cp_wait<1>();
        } else {
            cp_wait<0>();
        }
        __syncthreads();

        const unsigned int bufB = (st & 1) ? sB1 : sB0;
        const unsigned int b_base = bufB + b_lane_off;

        float acc[2][8][4];
        #pragma unroll
        for (int mt = 0; mt < 2; mt++) {
            #pragma unroll
            for (int nt = 0; nt < 8; nt++) {
                acc[mt][nt][0] = 0.0f; acc[mt][nt][1] = 0.0f;
                acc[mt][nt][2] = 0.0f; acc[mt][nt][3] = 0.0f;
            }
        }

        #pragma unroll
        for (int kt = 0; kt < 8; kt++) {
            unsigned int a0[4], a1[4];
            ldsm_x4(a0, a_addr0 + kt * 32);
            ldsm_x4(a1, a_addr1 + kt * 32);
            #pragma unroll
            for (int p = 0; p < 4; p++) {
                unsigned int bfr[4];           // {b0,b1} for nt=2p, {b0,b1} for nt=2p+1
                ldsm_x4(bfr, b_base + p * (16 * ROWB) + kt * 32);
                mma_16816(acc[0][2 * p],     a0, bfr);
                mma_16816(acc[1][2 * p],     a1, bfr);
                mma_16816(acc[0][2 * p + 1], a0, bfr + 2);
                mma_16816(acc[1][2 * p + 1], a1, bfr + 2);
            }
        }

        // fold s-tile into running per-row maxima
        float m0 = -3.0e38f, m1 = -3.0e38f, m2 = -3.0e38f, m3 = -3.0e38f;
        #pragma unroll
        for (int nt = 0; nt < 8; nt++) {
            m0 = fmaxf(m0, fmaxf(acc[0][nt][0], acc[0][nt][1]));
            m1 = fmaxf(m1, fmaxf(acc[0][nt][2], acc[0][nt][3]));
            m2 = fmaxf(m2, fmaxf(acc[1][nt][0], acc[1][nt][1]));
            m3 = fmaxf(m3, fmaxf(acc[1][nt][2], acc[1][nt][3]));
        }
        rmax00 = fmaxf(rmax00, m0); rmax01 = fmaxf(rmax01, m1);
        rmax10 = fmaxf(rmax10, m2); rmax11 = fmaxf(rmax11, m3);

        __syncthreads();   // compute done before this buffer is refilled
    }

    // cross-lane max: lanes l^1, l^2 hold other columns of the same row
    {
        float v;
        v = rmax00; v = fmaxf(v, __shfl_xor_sync(0xffffffffu, v, 1));
        v = fmaxf(v, __shfl_xor_sync(0xffffffffu, v, 2)); rmax00 = v;
        v = rmax01; v = fmaxf(v, __shfl_xor_sync(0xffffffffu, v, 1));
        v = fmaxf(v, __shfl_xor_sync(0xffffffffu, v, 2)); rmax01 = v;
        v = rmax10; v = fmaxf(v, __shfl_xor_sync(0xffffffffu, v, 1));
        v = fmaxf(v, __shfl_xor_sync(0xffffffffu, v, 2)); rmax10 = v;
        v = rmax11; v = fmaxf(v, __shfl_xor_sync(0xffffffffu, v, 1));
        v = fmaxf(v, __shfl_xor_sync(0xffffffffu, v, 2)); rmax11 = v;
    }
    if ((lane & 3) == 0) {
        const int rg = lane >> 2;
        float* rbuf = redbuf + wn * 128 + wm * 32;
        rbuf[rg]          = rmax00;
        rbuf[rg + 8]      = rmax01;
        rbuf[16 + rg]     = rmax10;
        rbuf[16 + rg + 8] = rmax11;
    }
    __syncthreads();

    if (tid < 128) {
        float m = fmaxf(redbuf[tid], redbuf[128 + tid]);
        #pragma unroll
        for (int o = 16; o; o >>= 1) {
            m += __shfl_xor_sync(0xffffffffu, m, o);
        }
        if (lane == 0) g_mscores[(rt * 4 + warp) * B + c] = m;
    }
}

// ---------------------------------------------------------------------------
// Kernel 3: epilogues. 1024 threads, 32 warps, warp w handles b = w, w+32.
// ---------------------------------------------------------------------------
__global__ void __launch_bounds__(1024) k_final(float* __restrict__ out) {
    __shared__ float s_sv[32];
    __shared__ float s_mv[32];
    const int warp = threadIdx.x >> 5;
    const int lane = threadIdx.x & 31;

    float sv = 0.0f, mv = 0.0f;
    #pragma unroll
    for (int i = 0; i < 2; i++) {
        const int b = warp + i * 32;

        // ---- single-vector CE term: lane l owns columns l and l+32 ----
        float v0 = 0.0f, v1 = 0.0f;
        #pragma unroll
        for (int kc = 0; kc < KSPLIT; kc++) {
            const float* p = g_part + (kc * B + b) * B;
            v0 += p[lane];
            v1 += p[lane + 32];
        }
        float mx = fmaxf(v0, v1);
        #pragma unroll
        for (int o = 16; o; o >>= 1) {
            mx = fmaxf(mx, __shfl_xor_sync(0xffffffffu, mx, o));
        }
        float se = expf(v0 - mx) + expf(v1 - mx);
        #pragma unroll
        for (int o = 16; o; o >>= 1) {
            se += __shfl_xor_sync(0xffffffffu, se, o);
        }
        float diag = __shfl_sync(0xffffffffu, (b < 32) ? v0 : v1, b & 31);
        sv += mx + logf(se) - diag;

        // ---- multi-vector margin term ----
        const float* mrow = g_mscores + b * B;
        float m0 = mrow[lane];
        float m1 = mrow[lane + 32];
        float pos = __shfl_sync(0xffffffffu, (b < 32) ? m0 : m1, b & 31);
        float n0 = (lane == b)      ? -3.0e38f : m0;
        float n1 = (lane + 32 == b) ? -3.0e38f : m1;
        float neg = fmaxf(n0, n1);
        #pragma unroll
        for (int o = 16; o; o >>= 1) {
            neg = fmaxf(neg, __shfl_xor_sync(0xffffffffu, neg, o));
        }
        float x = neg - pos;
        mv += fmaxf(x, 0.0f) + log1pf(expf(-fabsf(x)));
    }

    if (lane == 0) { s_sv[warp] = sv; s_mv[warp] = mv; }
    __syncthreads();
    if (warp == 0) {
        float SV = s_sv[lane];
        float MV = s_mv[lane];
        #pragma unroll
        for (int o = 16; o; o >>= 1) {
            SV += __shfl_xor_sync(0xffffffffu, SV, o);
            MV += __shfl_xor_sync(0xffffffffu, MV, o);
        }
        if (lane == 0) out[0] = ALPHA * SV + (1.0f - ALPHA) * (MV / B);
    }
}

// ---------------------------------------------------------------------------
extern "C" void kernel_launch(void* const* d_in, const int* in_sizes, int n_in,
                              void* d_out, int out_size) {
    const float* q_single = (const float*)d_in[0];  // [64, 1024]
    const float* d_single = (const float*)d_in[1];  // [64, 1024]
    const float* q_multi  = (const float*)d_in[2];  // [64, 32, 128]
    const float* d_multi  = (const float*)d_in[3];  // [64, 1024, 128]
    float* out = (float*)d_out;

    cudaFuncSetAttribute(k_multi_tc, cudaFuncAttributeMaxDynamicSharedMemorySize,
                         SMEM_TOT);

    k_prep<<<NCONV + NSING, 256>>>((const float4*)d_multi, (const float4*)q_multi,
                                   q_single, d_single);
    k_multi_tc<<<dim3(16, B), 256, SMEM_TOT>>>();
    k_final<<<1, 1024>>>(out);
}